// round 12
// baseline (speedup 1.0000x reference)
#include <cuda_runtime.h>
#include <cuda_bf16.h>
#include <mma.h>
#include <cstdint>
#include <math.h>

using namespace nvcuda;

#define BB    8
#define TT    1024
#define HH    768
#define HD    384
#define GG    1536            // 4*HD gates per direction
#define SS    16
#define NBD   48              // blocks per direction in recurrence
#define GPB   32              // gate rows per block (GG/NBD)
#define CPB   8               // h columns per block

// packed f32x2 helpers (sm_103a)
#define FMA2(d, a, b) asm("fma.rn.f32x2 %0, %1, %2, %0;" : "+l"(d) : "l"(a), "l"(b))
#define ADD2(d, a)    asm("add.rn.f32x2 %0, %1, %0;" : "+l"(d) : "l"(a))

// ---------------- device scratch (no allocation allowed) ----------------
__device__ __align__(16) __nv_bfloat16 g_x_bf[(size_t)BB * TT * HH];        // layer input (bf16)
__device__ __align__(16) __nv_bfloat16 g_wbf[2][(size_t)2 * GG * HH];       // W_ih bf16 per layer (fwd rows then bwd rows)
__device__ __align__(16) float         g_gx[(size_t)BB * TT * 2 * GG];      // input projections [8192][3072]
__device__ __align__(16) float         g_enc[(size_t)BB * TT * HH];         // fp32 layer output
__device__ __align__(16) float         g_h[2 * 2 * HD * BB];                // [parity][dir][k][b]
__device__ int                         g_flags[2][2][NBD];                  // [layer][dir][block]

// ---------------- tiny kernels ----------------
__global__ void init_flags_kernel() {
    int i = threadIdx.x;
    if (i < 2 * 2 * NBD) ((int*)g_flags)[i] = 0;
}

__global__ void emb_kernel(const int* __restrict__ ids, const float* __restrict__ emb) {
    int row = blockIdx.x;                         // b*T + t
    int id  = ids[row];
    const float* src = emb + (size_t)id * HH;
    __nv_bfloat16* dst = g_x_bf + (size_t)row * HH;
    for (int i = threadIdx.x; i < HH; i += blockDim.x)
        dst[i] = __float2bfloat16_rn(src[i]);
}

__global__ void conv_w_kernel(const float* __restrict__ wf, const float* __restrict__ wb, int layer) {
    int i = blockIdx.x * blockDim.x + threadIdx.x;     // over 2*GG*HH = 2359296
    if (i < 2 * GG * HH) {
        float v = (i < GG * HH) ? wf[i] : wb[i - GG * HH];
        g_wbf[layer][i] = __float2bfloat16_rn(v);
    }
}

// ---------------- input-projection GEMM: gx[8192,3072] = X[8192,768] * W[3072,768]^T ----------------
__global__ __launch_bounds__(256) void gemm_bf16_kernel(const __nv_bfloat16* __restrict__ Bw) {
    __shared__ __align__(16) __nv_bfloat16 As[64][48];
    __shared__ __align__(16) __nv_bfloat16 Bs[128][48];

    const __nv_bfloat16* __restrict__ A = g_x_bf;
    float* __restrict__ C = g_gx;

    int tid = threadIdx.x;
    int m0 = blockIdx.y * 64;
    int n0 = blockIdx.x * 128;
    int warp = tid >> 5;
    int wm = warp >> 2, wn = warp & 3;      // 2 x 4 warps

    wmma::fragment<wmma::accumulator, 16, 16, 16, float> acc[2][2];
#pragma unroll
    for (int i = 0; i < 2; i++)
#pragma unroll
        for (int j = 0; j < 2; j++) wmma::fill_fragment(acc[i][j], 0.0f);

    for (int k0 = 0; k0 < HH; k0 += 32) {
        {
            int r = tid >> 2, c = (tid & 3) * 8;   // 64 rows x 32 k
            *(uint4*)&As[r][c] = *(const uint4*)&A[(size_t)(m0 + r) * HH + k0 + c];
        }
#pragma unroll
        for (int i = 0; i < 2; i++) {
            int idx = tid + i * 256;
            int r = idx >> 2, c = (idx & 3) * 8;   // 128 rows x 32 k
            *(uint4*)&Bs[r][c] = *(const uint4*)&Bw[(size_t)(n0 + r) * HH + k0 + c];
        }
        __syncthreads();
#pragma unroll
        for (int kf = 0; kf < 32; kf += 16) {
            wmma::fragment<wmma::matrix_a, 16, 16, 16, __nv_bfloat16, wmma::row_major> af[2];
            wmma::fragment<wmma::matrix_b, 16, 16, 16, __nv_bfloat16, wmma::col_major> bf[2];
            wmma::load_matrix_sync(af[0], &As[wm * 32][kf], 48);
            wmma::load_matrix_sync(af[1], &As[wm * 32 + 16][kf], 48);
            wmma::load_matrix_sync(bf[0], &Bs[wn * 32][kf], 48);
            wmma::load_matrix_sync(bf[1], &Bs[wn * 32 + 16][kf], 48);
#pragma unroll
            for (int i = 0; i < 2; i++)
#pragma unroll
                for (int j = 0; j < 2; j++)
                    wmma::mma_sync(acc[i][j], af[i], bf[j], acc[i][j]);
        }
        __syncthreads();
    }
#pragma unroll
    for (int i = 0; i < 2; i++)
#pragma unroll
        for (int j = 0; j < 2; j++)
            wmma::store_matrix_sync(&C[(size_t)(m0 + wm * 32 + i * 16) * (2 * GG) + n0 + wn * 32 + j * 16],
                                    acc[i][j], 2 * GG, wmma::mem_row_major);
}

// ---------------- recurrence: 96 persistent blocks (48/dir), flag barrier, W in registers ---------
// Thread org: warp w owns gate rows gl = 4w..4w+3; lane = gr*8+ks (gr = gate-in-warp, ks = k-slice).
// Each thread: W_hh[grow][ks*48 .. ks*48+48) pre-packed (dup) in 48 b64 regs; accumulates all 8
// batches as 4 f32x2; reduce-scatter over the 8 ks lanes lands (gl, b=ks) on each lane.
__global__ __launch_bounds__(256) void recur_kernel(
    int layer,
    const float* __restrict__ whh_f, const float* __restrict__ whh_b,
    const float* __restrict__ bih_f, const float* __restrict__ bhh_f,
    const float* __restrict__ bih_b, const float* __restrict__ bhh_b)
{
    __shared__ __align__(16) float h_sh[HD * BB];   // [k][b]
    __shared__ float gate_sh[GPB * BB];             // [gl][b]
    __shared__ float c_sh[64];                      // [c][b]

    int tid = threadIdx.x;
    int dir = blockIdx.x / NBD;             // 0 fwd, 1 bwd
    int bi  = blockIdx.x - dir * NBD;
    int col0 = bi * CPB;

    int warp = tid >> 5, lane = tid & 31;
    int gr = lane >> 3, ks = lane & 7;
    int gl = warp * 4 + gr;
    int grow = (gl >> 3) * HD + col0 + (gl & 7);

    const float* whh = dir ? whh_b : whh_f;
    float bias_r = dir ? (bih_b[grow] + bhh_b[grow]) : (bih_f[grow] + bhh_f[grow]);

    // W slice into packed registers (loop-invariant across all 1024 steps)
    unsigned long long w2[48];
#pragma unroll
    for (int kk = 0; kk < 48; kk++) {
        float wv = whh[(size_t)grow * HD + ks * 48 + kk];
        unsigned int u = __float_as_uint(wv);
        asm("mov.b64 %0, {%1, %1};" : "=l"(w2[kk]) : "r"(u));
    }

    int* myflag = &g_flags[layer][dir][bi];
    int poll_j = tid >> 2;                          // tid<192: slice to poll+copy
    int* pollflag = &g_flags[layer][dir][poll_j < NBD ? poll_j : 0];

    if (tid < 64) c_sh[tid] = 0.0f;

    for (int ti = 0; ti < TT; ++ti) {
        int t = dir ? (TT - 1 - ti) : ti;

        // prefetch input-projection value for (gl, b=ks) — independent of h, covers poll latency
        float gxv = __ldg(&g_gx[(size_t)(ks * TT + t) * (2 * GG) + dir * GG + grow]);

        if (ti == 0) {
            for (int i = tid; i < HD * BB; i += 256) h_sh[i] = 0.0f;
        } else {
            if (tid < 192) {
                int v;
                do {
                    asm volatile("ld.acquire.gpu.b32 %0, [%1];" : "=r"(v) : "l"(pollflag) : "memory");
                    if (v < ti) __nanosleep(32);
                } while (v < ti);
                // copy my 16 floats of slice poll_j (slice = 64 floats = cols [poll_j*8, +8) x 8 b)
                const float4* s4 = (const float4*)(g_h + ((size_t)(ti & 1) * 2 + dir) * (HD * BB)
                                                   + poll_j * 64 + (tid & 3) * 16);
                float4* d4 = (float4*)(h_sh + poll_j * 64 + (tid & 3) * 16);
#pragma unroll
                for (int q = 0; q < 4; q++) d4[q] = __ldcg(&s4[q]);
            }
        }
        __syncthreads();

        // packed matvec: acc pairs (b0b1, b2b3, b4b5, b6b7)
        unsigned long long a0 = 0ull, a1 = 0ull, a2 = 0ull, a3 = 0ull;
        const ulonglong2* h2 = (const ulonglong2*)h_sh + ks * 96;   // k-slice base (2 u64x2 per k)
#pragma unroll
        for (int kk = 0; kk < 48; kk++) {
            ulonglong2 hva = h2[2 * kk];
            ulonglong2 hvb = h2[2 * kk + 1];
            FMA2(a0, w2[kk], hva.x);
            FMA2(a1, w2[kk], hva.y);
            FMA2(a2, w2[kk], hvb.x);
            FMA2(a3, w2[kk], hvb.y);
        }

        // reduce-scatter over 8 ks lanes -> lane ends holding (gl, b=ks)
        // round xor 4: keep pairs whose (b&4) matches (ks&4)
        {
            unsigned long long s0 = (ks & 4) ? a0 : a2;
            unsigned long long s1 = (ks & 4) ? a1 : a3;
            unsigned long long r0 = __shfl_xor_sync(0xFFFFFFFFu, s0, 4);
            unsigned long long r1 = __shfl_xor_sync(0xFFFFFFFFu, s1, 4);
            unsigned long long k0 = (ks & 4) ? a2 : a0;
            unsigned long long k1 = (ks & 4) ? a3 : a1;
            ADD2(k0, r0);
            ADD2(k1, r1);
            // round xor 2: keep pair whose (b&2) matches (ks&2)
            unsigned long long s2 = (ks & 2) ? k0 : k1;
            unsigned long long r2 = __shfl_xor_sync(0xFFFFFFFFu, s2, 2);
            unsigned long long k2 = (ks & 2) ? k1 : k0;
            ADD2(k2, r2);
            // round xor 1: keep float whose (b&1) matches (ks&1)
            unsigned int ulo, uhi;
            asm("mov.b64 {%0, %1}, %2;" : "=r"(ulo), "=r"(uhi) : "l"(k2));
            float lo = __uint_as_float(ulo), hi = __uint_as_float(uhi);
            float s3 = (ks & 1) ? lo : hi;
            float r3 = __shfl_xor_sync(0xFFFFFFFFu, s3, 1);
            float gsum = ((ks & 1) ? hi : lo) + r3 + gxv + bias_r;
            gate_sh[gl * 8 + ks] = gsum;
        }
        __syncthreads();

        // finalize: 64 threads own (column c, batch b)
        if (tid < 64) {
            int c = tid >> 3, b = tid & 7;
            float iv = gate_sh[(0 * 8 + c) * 8 + b];
            float fv = gate_sh[(1 * 8 + c) * 8 + b];
            float gv = gate_sh[(2 * 8 + c) * 8 + b];
            float ov = gate_sh[(3 * 8 + c) * 8 + b];
            float si = __fdividef(1.0f, 1.0f + __expf(-iv));
            float sf = __fdividef(1.0f, 1.0f + __expf(-fv));
            float so = __fdividef(1.0f, 1.0f + __expf(-ov));
            float tg = 1.0f - __fdividef(2.0f, __expf(2.0f * gv) + 1.0f);
            float cn = sf * c_sh[tid] + si * tg;
            float th = 1.0f - __fdividef(2.0f, __expf(2.0f * cn) + 1.0f);
            float hn = so * th;
            c_sh[tid] = cn;
            g_h[((size_t)((ti + 1) & 1) * 2 + dir) * (HD * BB) + (col0 + c) * 8 + b] = hn;
            size_t eidx = (size_t)(b * TT + t) * HH + dir * HD + col0 + c;
            g_enc[eidx]  = hn;
            g_x_bf[eidx] = __float2bfloat16_rn(hn);
        }
        __syncthreads();
        if (tid == 0)
            asm volatile("st.release.gpu.b32 [%0], %1;" :: "l"(myflag), "r"(ti + 1) : "memory");
    }
}

// ---------------- segment mean pool + MLP scorer ----------------
__global__ __launch_bounds__(256) void pool_mlp_kernel(
    const int* __restrict__ sb,
    const float* __restrict__ w1, const float* __restrict__ b1,
    const float* __restrict__ w2, const float* __restrict__ b2,
    float* __restrict__ out)
{
    __shared__ float mean_sh[HH];
    __shared__ float red[8];

    int b = blockIdx.x >> 4, s = blockIdx.x & 15;
    int tid = threadIdx.x;
    int end = sb[b * SS + s];
    int start = s ? sb[b * SS + s - 1] : 0;
    float inv = 1.0f / fmaxf((float)(end - start), 1.0f);

    float a0 = 0.f, a1 = 0.f, a2 = 0.f;
    for (int t = start; t < end; t++) {
        const float* row = g_enc + (size_t)(b * TT + t) * HH;
        a0 += row[tid]; a1 += row[tid + 256]; a2 += row[tid + 512];
    }
    mean_sh[tid] = a0 * inv; mean_sh[tid + 256] = a1 * inv; mean_sh[tid + 512] = a2 * inv;
    __syncthreads();

    int warp = tid >> 5, lane = tid & 31;
    float wpart = 0.f;
    for (int j = warp; j < HD; j += 8) {
        const float* wr = w1 + (size_t)j * HH;
        float acc = 0.f;
        for (int d = lane; d < HH; d += 32) acc += mean_sh[d] * wr[d];
#pragma unroll
        for (int o = 16; o; o >>= 1) acc += __shfl_xor_sync(0xFFFFFFFFu, acc, o);
        if (lane == 0) {
            float h = fmaxf(acc + b1[j], 0.0f);
            wpart += h * w2[j];
        }
    }
    if (lane == 0) red[warp] = wpart;
    __syncthreads();
    if (tid == 0) {
        float h2 = b2[0];
#pragma unroll
        for (int w = 0; w < 8; w++) h2 += red[w];
        out[b * SS + s] = 1.0f / (1.0f + expf(-h2));
    }
}

__global__ void min_kernel(float* __restrict__ out) {
    int b = threadIdx.x;
    if (b < BB) {
        float m = 1e30f;
        for (int s = 0; s < SS; s++) {
            float r = out[b * SS + s];
            float mask = (r > 0.0f) ? 1.0f : 0.0f;
            float v = r * mask + (1.0f - mask);
            m = fminf(m, v);
        }
        out[BB * SS + b] = m;
    }
}

// ---------------- launch ----------------
extern "C" void kernel_launch(void* const* d_in, const int* in_sizes, int n_in,
                              void* d_out, int out_size) {
    const int*   ids = (const int*)d_in[0];
    const int*   sb  = (const int*)d_in[1];
    const float* emb = (const float*)d_in[2];
    const float* w_ih_l0f = (const float*)d_in[3];
    const float* w_hh_l0f = (const float*)d_in[4];
    const float* b_ih_l0f = (const float*)d_in[5];
    const float* b_hh_l0f = (const float*)d_in[6];
    const float* w_ih_l0b = (const float*)d_in[7];
    const float* w_hh_l0b = (const float*)d_in[8];
    const float* b_ih_l0b = (const float*)d_in[9];
    const float* b_hh_l0b = (const float*)d_in[10];
    const float* w_ih_l1f = (const float*)d_in[11];
    const float* w_hh_l1f = (const float*)d_in[12];
    const float* b_ih_l1f = (const float*)d_in[13];
    const float* b_hh_l1f = (const float*)d_in[14];
    const float* w_ih_l1b = (const float*)d_in[15];
    const float* w_hh_l1b = (const float*)d_in[16];
    const float* b_ih_l1b = (const float*)d_in[17];
    const float* b_hh_l1b = (const float*)d_in[18];
    const float* w1 = (const float*)d_in[19];
    const float* b1 = (const float*)d_in[20];
    const float* w2 = (const float*)d_in[21];
    const float* b2 = (const float*)d_in[22];
    float* out = (float*)d_out;

    init_flags_kernel<<<1, 256>>>();
    emb_kernel<<<BB * TT, 256>>>(ids, emb);

    int nconv = 2 * GG * HH;
    conv_w_kernel<<<(nconv + 255) / 256, 256>>>(w_ih_l0f, w_ih_l0b, 0);
    conv_w_kernel<<<(nconv + 255) / 256, 256>>>(w_ih_l1f, w_ih_l1b, 1);

    dim3 ggrid(2 * GG / 128, BB * TT / 64);   // (24, 128)

    __nv_bfloat16* wptr = nullptr;
    cudaGetSymbolAddress((void**)&wptr, g_wbf);

    // layer 0
    gemm_bf16_kernel<<<ggrid, 256>>>(wptr);
    recur_kernel<<<2 * NBD, 256>>>(0, w_hh_l0f, w_hh_l0b,
                                   b_ih_l0f, b_hh_l0f, b_ih_l0b, b_hh_l0b);
    // layer 1
    gemm_bf16_kernel<<<ggrid, 256>>>(wptr + (size_t)2 * GG * HH);
    recur_kernel<<<2 * NBD, 256>>>(1, w_hh_l1f, w_hh_l1b,
                                   b_ih_l1f, b_hh_l1f, b_ih_l1b, b_hh_l1b);

    pool_mlp_kernel<<<BB * SS, 256>>>(sb, w1, b1, w2, b2, out);
    if (out_size >= BB * SS + BB)
        min_kernel<<<1, 32>>>(out);
}

// round 14
// speedup vs baseline: 3.5636x; 3.5636x over previous
#include <cuda_runtime.h>
#include <cuda_bf16.h>
#include <mma.h>
#include <cstdint>
#include <math.h>

using namespace nvcuda;

#define BB    8
#define TT    1024
#define HH    768
#define HD    384
#define GG    1536            // 4*HD gates per direction
#define SS    16
#define NBD   48              // blocks per direction in recurrence
#define GPB   32              // gate rows per block (GG/NBD)
#define CPB   8               // h columns per block

// packed f32x2 helpers (sm_103a)
#define FMA2(d, a, b) asm("fma.rn.f32x2 %0, %1, %2, %0;" : "+l"(d) : "l"(a), "l"(b))

// ---------------- device scratch (no allocation allowed) ----------------
__device__ __align__(16) __nv_bfloat16 g_x_bf[(size_t)BB * TT * HH];        // layer input (bf16)
__device__ __align__(16) __nv_bfloat16 g_wbf[2][(size_t)2 * GG * HH];       // W_ih bf16 per layer
__device__ __align__(16) float         g_gx[(size_t)BB * TT * 2 * GG];      // input projections [8192][3072]
__device__ __align__(16) float         g_enc[(size_t)BB * TT * HH];         // fp32 layer output
__device__ __align__(16) float         g_h[2 * 2 * HD * BB];                // [parity][dir][k][b]
__device__ int                         g_flags[2][2][NBD];                  // [layer][dir][block]

// ---------------- tiny kernels ----------------
__global__ void init_flags_kernel() {
    int i = threadIdx.x;
    if (i < 2 * 2 * NBD) ((int*)g_flags)[i] = 0;
}

__global__ void emb_kernel(const int* __restrict__ ids, const float* __restrict__ emb) {
    int row = blockIdx.x;                         // b*T + t
    int id  = ids[row];
    const float* src = emb + (size_t)id * HH;
    __nv_bfloat16* dst = g_x_bf + (size_t)row * HH;
    for (int i = threadIdx.x; i < HH; i += blockDim.x)
        dst[i] = __float2bfloat16_rn(src[i]);
}

__global__ void conv_w_kernel(const float* __restrict__ wf, const float* __restrict__ wb, int layer) {
    int i = blockIdx.x * blockDim.x + threadIdx.x;     // over 2*GG*HH = 2359296
    if (i < 2 * GG * HH) {
        float v = (i < GG * HH) ? wf[i] : wb[i - GG * HH];
        g_wbf[layer][i] = __float2bfloat16_rn(v);
    }
}

// ---------------- input-projection GEMM: gx[8192,3072] = X[8192,768] * W[3072,768]^T ----------------
__global__ __launch_bounds__(256) void gemm_bf16_kernel(const __nv_bfloat16* __restrict__ Bw) {
    __shared__ __align__(16) __nv_bfloat16 As[64][48];
    __shared__ __align__(16) __nv_bfloat16 Bs[128][48];

    const __nv_bfloat16* __restrict__ A = g_x_bf;
    float* __restrict__ C = g_gx;

    int tid = threadIdx.x;
    int m0 = blockIdx.y * 64;
    int n0 = blockIdx.x * 128;
    int warp = tid >> 5;
    int wm = warp >> 2, wn = warp & 3;      // 2 x 4 warps

    wmma::fragment<wmma::accumulator, 16, 16, 16, float> acc[2][2];
#pragma unroll
    for (int i = 0; i < 2; i++)
#pragma unroll
        for (int j = 0; j < 2; j++) wmma::fill_fragment(acc[i][j], 0.0f);

    for (int k0 = 0; k0 < HH; k0 += 32) {
        {
            int r = tid >> 2, c = (tid & 3) * 8;   // 64 rows x 32 k
            *(uint4*)&As[r][c] = *(const uint4*)&A[(size_t)(m0 + r) * HH + k0 + c];
        }
#pragma unroll
        for (int i = 0; i < 2; i++) {
            int idx = tid + i * 256;
            int r = idx >> 2, c = (idx & 3) * 8;   // 128 rows x 32 k
            *(uint4*)&Bs[r][c] = *(const uint4*)&Bw[(size_t)(n0 + r) * HH + k0 + c];
        }
        __syncthreads();
#pragma unroll
        for (int kf = 0; kf < 32; kf += 16) {
            wmma::fragment<wmma::matrix_a, 16, 16, 16, __nv_bfloat16, wmma::row_major> af[2];
            wmma::fragment<wmma::matrix_b, 16, 16, 16, __nv_bfloat16, wmma::col_major> bf[2];
            wmma::load_matrix_sync(af[0], &As[wm * 32][kf], 48);
            wmma::load_matrix_sync(af[1], &As[wm * 32 + 16][kf], 48);
            wmma::load_matrix_sync(bf[0], &Bs[wn * 32][kf], 48);
            wmma::load_matrix_sync(bf[1], &Bs[wn * 32 + 16][kf], 48);
#pragma unroll
            for (int i = 0; i < 2; i++)
#pragma unroll
                for (int j = 0; j < 2; j++)
                    wmma::mma_sync(acc[i][j], af[i], bf[j], acc[i][j]);
        }
        __syncthreads();
    }
#pragma unroll
    for (int i = 0; i < 2; i++)
#pragma unroll
        for (int j = 0; j < 2; j++)
            wmma::store_matrix_sync(&C[(size_t)(m0 + wm * 32 + i * 16) * (2 * GG) + n0 + wn * 32 + j * 16],
                                    acc[i][j], 2 * GG, wmma::mem_row_major);
}

// ---------------- recurrence: 96 persistent blocks (48/dir) ----------------
// Thread org (R11, conflict-free): warp = k-chunk of 48, lane = gate-local row gl (0..31).
// h_sh is [k][b]; all lanes of a warp read the SAME h address (broadcast). W from smem float4,
// dup'd to b64 and used in fma.rn.f32x2 over batch pairs: 192 FMA2/thread/step.
// smem floats: w 12288 | h 3072 | part 2048 | gate 256 | bias 32 | c 64 = 17760 (71040 B)
#define RSMEM_FLOATS 17760
#define RSMEM_BYTES  (RSMEM_FLOATS * 4)

__global__ __launch_bounds__(256) void recur_kernel(
    int layer,
    const float* __restrict__ whh_f, const float* __restrict__ whh_b,
    const float* __restrict__ bih_f, const float* __restrict__ bhh_f,
    const float* __restrict__ bih_b, const float* __restrict__ bhh_b)
{
    extern __shared__ __align__(16) float sm[];
    float* w_sm    = sm;            // [kq 0..95][gl 0..31] float4
    float* h_sh    = sm + 12288;    // [k 0..383][b 0..7]
    float* part    = sm + 15360;    // [warp][gl][b]
    float* gate_sh = sm + 17408;    // [gl][b]
    float* bias_sh = sm + 17664;    // [gl]
    float* c_sh    = sm + 17696;    // [c][b]

    int tid = threadIdx.x;
    int dir = blockIdx.x / NBD;             // 0 fwd, 1 bwd
    int bi  = blockIdx.x - dir * NBD;
    int col0 = bi * CPB;

    const float* whh = dir ? whh_b : whh_f;

    // stage W_hh slice: gl -> global gate row (gl>>3)*HD + col0 + (gl&7)
    for (int i = tid; i < GPB * HD; i += 256) {
        int gl = i / HD, k = i - gl * HD;
        int grow = (gl >> 3) * HD + col0 + (gl & 7);
        w_sm[(k >> 2) * 128 + gl * 4 + (k & 3)] = whh[(size_t)grow * HD + k];
    }
    if (tid < GPB) {
        int gl = tid;
        int grow = (gl >> 3) * HD + col0 + (gl & 7);
        bias_sh[gl] = dir ? (bih_b[grow] + bhh_b[grow]) : (bih_f[grow] + bhh_f[grow]);
    }
    if (tid < 64) c_sh[tid] = 0.0f;
    __syncthreads();

    int warp = tid >> 5, lane = tid & 31;
    int* myflag = &g_flags[layer][dir][bi];
    int* pollflag = &g_flags[layer][dir][tid < NBD ? tid : 0];
    const float4* w4 = (const float4*)w_sm;
    const ulonglong2* h2 = (const ulonglong2*)h_sh;
    float4* part4 = (float4*)part;

    int gl_r = tid >> 3, b_r = tid & 7;     // reduce-stage role
    int grow_r = (gl_r >> 3) * HD + col0 + (gl_r & 7);

    for (int ti = 0; ti < TT; ++ti) {
        int t = dir ? (TT - 1 - ti) : ti;

        // prefetch input-projection value (independent of h) — in flight during poll/copy
        float gxv = __ldg(&g_gx[(size_t)(b_r * TT + t) * (2 * GG) + dir * GG + grow_r]);

        if (ti == 0) {
            for (int i = tid; i < HD * BB; i += 256) h_sh[i] = 0.0f;
            __syncthreads();
        } else {
            if (tid < NBD) {                      // 48 lanes poll 48 distinct flags in parallel
                int v;
                do {
                    asm volatile("ld.acquire.gpu.b32 %0, [%1];" : "=r"(v) : "l"(pollflag) : "memory");
                    if (v < ti) __nanosleep(32);
                } while (v < ti);
            }
            __syncthreads();
            const float4* src = (const float4*)(g_h + ((size_t)(ti & 1) * 2 + dir) * (HD * BB));
            float4* dst = (float4*)h_sh;
#pragma unroll
            for (int q = 0; q < 3; q++) dst[tid + q * 256] = __ldcg(&src[tid + q * 256]);
            __syncthreads();
        }

        // packed matvec over this warp's 48-k chunk; lane = gate row gl.
        unsigned long long a0 = 0ull, a1 = 0ull, a2 = 0ull, a3 = 0ull;   // (b0b1,b2b3,b4b5,b6b7)
        int kq0 = warp * 12;
#pragma unroll
        for (int kk = 0; kk < 12; kk++) {
            float4 wv = w4[(kq0 + kk) * 32 + lane];      // lane-consecutive, conflict-free
            int k4 = (kq0 + kk) * 4;
#pragma unroll
            for (int j = 0; j < 4; j++) {
                float wj = j == 0 ? wv.x : (j == 1 ? wv.y : (j == 2 ? wv.z : wv.w));
                unsigned long long wd;
                unsigned int wu = __float_as_uint(wj);
                asm("mov.b64 %0, {%1, %1};" : "=l"(wd) : "r"(wu));
                ulonglong2 ha = h2[(k4 + j) * 2];        // broadcast (same addr all lanes)
                ulonglong2 hb = h2[(k4 + j) * 2 + 1];
                FMA2(a0, wd, ha.x);
                FMA2(a1, wd, ha.y);
                FMA2(a2, wd, hb.x);
                FMA2(a3, wd, hb.y);
            }
        }
        {
            float2 f0 = *(float2*)&a0, f1 = *(float2*)&a1, f2 = *(float2*)&a2, f3 = *(float2*)&a3;
            part4[(warp * 32 + lane) * 2]     = make_float4(f0.x, f0.y, f1.x, f1.y);
            part4[(warp * 32 + lane) * 2 + 1] = make_float4(f2.x, f2.y, f3.x, f3.y);
        }
        __syncthreads();

        // reduce across warps, add gx + bias
        float gsum = gxv + bias_sh[gl_r];
#pragma unroll
        for (int w = 0; w < 8; w++) gsum += part[w * 256 + tid];
        gate_sh[tid] = gsum;
        __syncthreads();

        // finalize: 64 threads own (column c, batch b)
        if (tid < 64) {
            int c = tid >> 3, b = tid & 7;
            float iv = gate_sh[(0 * 8 + c) * 8 + b];
            float fv = gate_sh[(1 * 8 + c) * 8 + b];
            float gv = gate_sh[(2 * 8 + c) * 8 + b];
            float ov = gate_sh[(3 * 8 + c) * 8 + b];
            float si = __fdividef(1.0f, 1.0f + __expf(-iv));
            float sf = __fdividef(1.0f, 1.0f + __expf(-fv));
            float so = __fdividef(1.0f, 1.0f + __expf(-ov));
            float tg = 1.0f - __fdividef(2.0f, __expf(2.0f * gv) + 1.0f);
            float cn = sf * c_sh[tid] + si * tg;
            float th = 1.0f - __fdividef(2.0f, __expf(2.0f * cn) + 1.0f);
            float hn = so * th;
            c_sh[tid] = cn;
            // [k][b] layout: 64 consecutive floats, coalesced
            g_h[((size_t)((ti + 1) & 1) * 2 + dir) * (HD * BB) + (col0 + c) * 8 + b] = hn;
            size_t eidx = (size_t)(b * TT + t) * HH + dir * HD + col0 + c;
            g_enc[eidx]  = hn;
            g_x_bf[eidx] = __float2bfloat16_rn(hn);
        }
        __syncthreads();
        if (tid == 0) {
            __threadfence();
            asm volatile("st.relaxed.gpu.b32 [%0], %1;" :: "l"(myflag), "r"(ti + 1) : "memory");
        }
    }
}

// ---------------- segment mean pool + MLP scorer ----------------
__global__ __launch_bounds__(256) void pool_mlp_kernel(
    const int* __restrict__ sb,
    const float* __restrict__ w1, const float* __restrict__ b1,
    const float* __restrict__ w2, const float* __restrict__ b2,
    float* __restrict__ out)
{
    __shared__ float mean_sh[HH];
    __shared__ float red[8];

    int b = blockIdx.x >> 4, s = blockIdx.x & 15;
    int tid = threadIdx.x;
    int end = sb[b * SS + s];
    int start = s ? sb[b * SS + s - 1] : 0;
    float inv = 1.0f / fmaxf((float)(end - start), 1.0f);

    float a0 = 0.f, a1 = 0.f, a2 = 0.f;
    for (int t = start; t < end; t++) {
        const float* row = g_enc + (size_t)(b * TT + t) * HH;
        a0 += row[tid]; a1 += row[tid + 256]; a2 += row[tid + 512];
    }
    mean_sh[tid] = a0 * inv; mean_sh[tid + 256] = a1 * inv; mean_sh[tid + 512] = a2 * inv;
    __syncthreads();

    int warp = tid >> 5, lane = tid & 31;
    float wpart = 0.f;
    for (int j = warp; j < HD; j += 8) {
        const float* wr = w1 + (size_t)j * HH;
        float acc = 0.f;
        for (int d = lane; d < HH; d += 32) acc += mean_sh[d] * wr[d];
#pragma unroll
        for (int o = 16; o; o >>= 1) acc += __shfl_xor_sync(0xFFFFFFFFu, acc, o);
        if (lane == 0) {
            float h = fmaxf(acc + b1[j], 0.0f);
            wpart += h * w2[j];
        }
    }
    if (lane == 0) red[warp] = wpart;
    __syncthreads();
    if (tid == 0) {
        float h2 = b2[0];
#pragma unroll
        for (int w = 0; w < 8; w++) h2 += red[w];
        out[b * SS + s] = 1.0f / (1.0f + expf(-h2));
    }
}

__global__ void min_kernel(float* __restrict__ out) {
    int b = threadIdx.x;
    if (b < BB) {
        float m = 1e30f;
        for (int s = 0; s < SS; s++) {
            float r = out[b * SS + s];
            float mask = (r > 0.0f) ? 1.0f : 0.0f;
            float v = r * mask + (1.0f - mask);
            m = fminf(m, v);
        }
        out[BB * SS + b] = m;
    }
}

// ---------------- launch ----------------
extern "C" void kernel_launch(void* const* d_in, const int* in_sizes, int n_in,
                              void* d_out, int out_size) {
    const int*   ids = (const int*)d_in[0];
    const int*   sb  = (const int*)d_in[1];
    const float* emb = (const float*)d_in[2];
    const float* w_ih_l0f = (const float*)d_in[3];
    const float* w_hh_l0f = (const float*)d_in[4];
    const float* b_ih_l0f = (const float*)d_in[5];
    const float* b_hh_l0f = (const float*)d_in[6];
    const float* w_ih_l0b = (const float*)d_in[7];
    const float* w_hh_l0b = (const float*)d_in[8];
    const float* b_ih_l0b = (const float*)d_in[9];
    const float* b_hh_l0b = (const float*)d_in[10];
    const float* w_ih_l1f = (const float*)d_in[11];
    const float* w_hh_l1f = (const float*)d_in[12];
    const float* b_ih_l1f = (const float*)d_in[13];
    const float* b_hh_l1f = (const float*)d_in[14];
    const float* w_ih_l1b = (const float*)d_in[15];
    const float* w_hh_l1b = (const float*)d_in[16];
    const float* b_ih_l1b = (const float*)d_in[17];
    const float* b_hh_l1b = (const float*)d_in[18];
    const float* w1 = (const float*)d_in[19];
    const float* b1 = (const float*)d_in[20];
    const float* w2 = (const float*)d_in[21];
    const float* b2 = (const float*)d_in[22];
    float* out = (float*)d_out;

    cudaFuncSetAttribute((const void*)recur_kernel,
                         cudaFuncAttributeMaxDynamicSharedMemorySize, RSMEM_BYTES);

    init_flags_kernel<<<1, 256>>>();
    emb_kernel<<<BB * TT, 256>>>(ids, emb);

    int nconv = 2 * GG * HH;
    conv_w_kernel<<<(nconv + 255) / 256, 256>>>(w_ih_l0f, w_ih_l0b, 0);
    conv_w_kernel<<<(nconv + 255) / 256, 256>>>(w_ih_l1f, w_ih_l1b, 1);

    dim3 ggrid(2 * GG / 128, BB * TT / 64);   // (24, 128)

    __nv_bfloat16* wptr = nullptr;
    cudaGetSymbolAddress((void**)&wptr, g_wbf);

    // layer 0
    gemm_bf16_kernel<<<ggrid, 256>>>(wptr);
    recur_kernel<<<2 * NBD, 256, RSMEM_BYTES>>>(0, w_hh_l0f, w_hh_l0b,
                                                b_ih_l0f, b_hh_l0f, b_ih_l0b, b_hh_l0b);
    // layer 1
    gemm_bf16_kernel<<<ggrid, 256>>>(wptr + (size_t)2 * GG * HH);
    recur_kernel<<<2 * NBD, 256, RSMEM_BYTES>>>(1, w_hh_l1f, w_hh_l1b,
                                                b_ih_l1f, b_hh_l1f, b_ih_l1b, b_hh_l1b);

    pool_mlp_kernel<<<BB * SS, 256>>>(sb, w1, b1, w2, b2, out);
    if (out_size >= BB * SS + BB)
        min_kernel<<<1, 32>>>(out);
}